// round 1
// baseline (speedup 1.0000x reference)
#include <cuda_runtime.h>

// PMLoss: PoseCNN point-matching loss.
// Inputs (metadata order): prediction [B,4C] f32, target [B,4C] f32,
// weight [B,4C] f32, points [C,P,3] f32, symmetry [C] f32. Output: scalar f32.

#define NB        128
#define NC        22
#define NP        1024
#define NCHUNK    4
#define NTHREADS  256          // == NP / NCHUNK : one p per thread
#define NPARTIAL  (NB * NCHUNK)

__device__ float g_partial[NPARTIAL];

__device__ __forceinline__ float warp_reduce_sum(float v) {
    v += __shfl_xor_sync(0xffffffffu, v, 16);
    v += __shfl_xor_sync(0xffffffffu, v, 8);
    v += __shfl_xor_sync(0xffffffffu, v, 4);
    v += __shfl_xor_sync(0xffffffffu, v, 2);
    v += __shfl_xor_sync(0xffffffffu, v, 1);
    return v;
}

__global__ __launch_bounds__(NTHREADS) void pm_loss_main(
    const float* __restrict__ pred, const float* __restrict__ tgt,
    const float* __restrict__ wgt,  const float* __restrict__ points,
    const float* __restrict__ sym)
{
    const int b     = blockIdx.x;
    const int chunk = blockIdx.y;
    const int tid   = threadIdx.x;

    __shared__ float4 s_pt[NP];      // target-rotated points + |pt|^2 (16 KB)
    __shared__ float  s_R[18];       // Rp[0..8], Rt[9..17]
    __shared__ int    s_cls;
    __shared__ float  s_issym;
    __shared__ float  s_warp[NTHREADS / 32];

    if (tid == 0) {
        // argmax over weight[b, c, 0] (first max, matching jnp.argmax)
        const float* w = wgt + b * 4 * NC;
        int cls = 0; float best = w[0];
        #pragma unroll
        for (int c = 1; c < NC; c++) {
            float v = w[4 * c];
            if (v > best) { best = v; cls = c; }
        }
        s_cls   = cls;
        s_issym = sym[cls];

        // predicted quaternion (normalized) -> Rp
        const float* qp = pred + b * 4 * NC + 4 * cls;
        float qw = qp[0], qx = qp[1], qy = qp[2], qz = qp[3];
        float inv = rsqrtf(qw*qw + qx*qx + qy*qy + qz*qz);
        qw *= inv; qx *= inv; qy *= inv; qz *= inv;
        s_R[0] = 1.f - 2.f*(qy*qy + qz*qz); s_R[1] = 2.f*(qx*qy - qw*qz); s_R[2] = 2.f*(qx*qz + qw*qy);
        s_R[3] = 2.f*(qx*qy + qw*qz); s_R[4] = 1.f - 2.f*(qx*qx + qz*qz); s_R[5] = 2.f*(qy*qz - qw*qx);
        s_R[6] = 2.f*(qx*qz - qw*qy); s_R[7] = 2.f*(qy*qz + qw*qx); s_R[8] = 1.f - 2.f*(qx*qx + qy*qy);

        // target quaternion (already unit-norm in the reference) -> Rt
        const float* qt = tgt + b * 4 * NC + 4 * cls;
        qw = qt[0]; qx = qt[1]; qy = qt[2]; qz = qt[3];
        s_R[ 9] = 1.f - 2.f*(qy*qy + qz*qz); s_R[10] = 2.f*(qx*qy - qw*qz); s_R[11] = 2.f*(qx*qz + qw*qy);
        s_R[12] = 2.f*(qx*qy + qw*qz); s_R[13] = 1.f - 2.f*(qx*qx + qz*qz); s_R[14] = 2.f*(qy*qz - qw*qx);
        s_R[15] = 2.f*(qx*qz - qw*qy); s_R[16] = 2.f*(qy*qz + qw*qx); s_R[17] = 1.f - 2.f*(qx*qx + qy*qy);
    }
    __syncthreads();

    const int cls = s_cls;
    const float* pts = points + (size_t)cls * NP * 3;

    // All threads: rotate all P points by Rt into smem, with squared norm in .w
    {
        const float r0 = s_R[ 9], r1 = s_R[10], r2 = s_R[11];
        const float r3 = s_R[12], r4 = s_R[13], r5 = s_R[14];
        const float r6 = s_R[15], r7 = s_R[16], r8 = s_R[17];
        #pragma unroll
        for (int q = tid; q < NP; q += NTHREADS) {
            float x = pts[3*q], y = pts[3*q + 1], z = pts[3*q + 2];
            float tx = r0*x + r1*y + r2*z;
            float ty = r3*x + r4*y + r5*z;
            float tz = r6*x + r7*y + r8*z;
            float nq = tx*tx + ty*ty + tz*tz;
            s_pt[q] = make_float4(tx, ty, tz, nq);
        }
    }
    __syncthreads();

    // This thread's predicted-rotated point (one p per thread, per chunk)
    const int p = chunk * NTHREADS + tid;
    float ppx, ppy, ppz;
    {
        const float r0 = s_R[0], r1 = s_R[1], r2 = s_R[2];
        const float r3 = s_R[3], r4 = s_R[4], r5 = s_R[5];
        const float r6 = s_R[6], r7 = s_R[7], r8 = s_R[8];
        float x = pts[3*p], y = pts[3*p + 1], z = pts[3*p + 2];
        ppx = r0*x + r1*y + r2*z;
        ppy = r3*x + r4*y + r5*z;
        ppz = r6*x + r7*y + r8*z;
    }

    float acc;
    if (s_issym > 0.f) {
        // min over q of |pp - pt_q|^2 = cp + min_q(nq - 2*dot)
        const float cp = ppx*ppx + ppy*ppy + ppz*ppz;
        const float BIG = 3.402823e38f;
        float m0 = BIG, m1 = BIG, m2 = BIG, m3 = BIG;
        #pragma unroll 4
        for (int q = 0; q < NP; q += 4) {
            float4 a = s_pt[q + 0];
            float4 bq = s_pt[q + 1];
            float4 cq = s_pt[q + 2];
            float4 dq = s_pt[q + 3];
            float d0 = fmaf(ppx, a.x,  fmaf(ppy, a.y,  ppz * a.z));
            float d1 = fmaf(ppx, bq.x, fmaf(ppy, bq.y, ppz * bq.z));
            float d2 = fmaf(ppx, cq.x, fmaf(ppy, cq.y, ppz * cq.z));
            float d3 = fmaf(ppx, dq.x, fmaf(ppy, dq.y, ppz * dq.z));
            m0 = fminf(m0, fmaf(-2.f, d0, a.w));
            m1 = fminf(m1, fmaf(-2.f, d1, bq.w));
            m2 = fminf(m2, fmaf(-2.f, d2, cq.w));
            m3 = fminf(m3, fmaf(-2.f, d3, dq.w));
        }
        acc = cp + fminf(fminf(m0, m1), fminf(m2, m3));
    } else {
        // pointwise |pp_p - pt_p|^2
        float4 t = s_pt[p];
        float dx = ppx - t.x, dy = ppy - t.y, dz = ppz - t.z;
        acc = dx*dx + dy*dy + dz*dz;
    }

    // Block reduction -> deterministic per-block partial
    float s = warp_reduce_sum(acc);
    if ((tid & 31) == 0) s_warp[tid >> 5] = s;
    __syncthreads();
    if (tid < 32) {
        float v = (tid < (NTHREADS / 32)) ? s_warp[tid] : 0.f;
        v = warp_reduce_sum(v);
        if (tid == 0) g_partial[b * NCHUNK + chunk] = v;
    }
}

__global__ __launch_bounds__(NPARTIAL) void pm_loss_reduce(float* __restrict__ out) {
    __shared__ float s_warp[NPARTIAL / 32];
    const int tid = threadIdx.x;
    float v = g_partial[tid];
    v = warp_reduce_sum(v);
    if ((tid & 31) == 0) s_warp[tid >> 5] = v;
    __syncthreads();
    if (tid < 32) {
        float t = (tid < (NPARTIAL / 32)) ? s_warp[tid] : 0.f;
        t = warp_reduce_sum(t);
        if (tid == 0) out[0] = t * (1.0f / (2.0f * (float)NB * (float)NP));
    }
}

extern "C" void kernel_launch(void* const* d_in, const int* in_sizes, int n_in,
                              void* d_out, int out_size) {
    const float* pred = (const float*)d_in[0];
    const float* tgt  = (const float*)d_in[1];
    const float* wgt  = (const float*)d_in[2];
    const float* pts  = (const float*)d_in[3];
    const float* sym  = (const float*)d_in[4];

    dim3 grid(NB, NCHUNK);
    pm_loss_main<<<grid, NTHREADS>>>(pred, tgt, wgt, pts, sym);
    pm_loss_reduce<<<1, NPARTIAL>>>((float*)d_out);
}

// round 3
// speedup vs baseline: 1.4159x; 1.4159x over previous
#include <cuda_runtime.h>

// PMLoss: PoseCNN point-matching loss, single fused kernel.
// Inputs: prediction [B,4C] f32, target [B,4C] f32, weight [B,4C] f32,
// points [C,P,3] f32, symmetry [C] f32. Output: scalar f32.

#define NB        128
#define NC        22
#define NP        1024
#define NPAIR     (NP / 2)
#define NCHUNK    8
#define NTHREADS  128                 // == NP / NCHUNK : one p per thread
#define NBLOCKS   (NB * NCHUNK)

#define FXSCALE   1099511627776.0     // 2^40 fixed-point scale

__device__ unsigned long long g_acc;     // zero-init at load; last block resets
__device__ unsigned int       g_count;   // zero-init at load; last block resets

__device__ __forceinline__ unsigned long long pack2(float lo, float hi) {
    unsigned long long r;
    asm("mov.b64 %0, {%1, %2};" : "=l"(r) : "f"(lo), "f"(hi));
    return r;
}
__device__ __forceinline__ void unpack2(unsigned long long v, float& lo, float& hi) {
    asm("mov.b64 {%0, %1}, %2;" : "=f"(lo), "=f"(hi) : "l"(v));
}
// Packed dual fp32 FMA (FFMA2) — only reachable via PTX fma.rn.f32x2.
__device__ __forceinline__ unsigned long long fma2(
    unsigned long long a, unsigned long long b, unsigned long long c) {
    unsigned long long d;
    asm("fma.rn.f32x2 %0, %1, %2, %3;" : "=l"(d) : "l"(a), "l"(b), "l"(c));
    return d;
}

__device__ __forceinline__ float warp_reduce_sum(float v) {
    v += __shfl_xor_sync(0xffffffffu, v, 16);
    v += __shfl_xor_sync(0xffffffffu, v, 8);
    v += __shfl_xor_sync(0xffffffffu, v, 4);
    v += __shfl_xor_sync(0xffffffffu, v, 2);
    v += __shfl_xor_sync(0xffffffffu, v, 1);
    return v;
}

__global__ __launch_bounds__(NTHREADS) void pm_loss_main(
    const float* __restrict__ pred, const float* __restrict__ tgt,
    const float* __restrict__ wgt,  const float* __restrict__ points,
    const float* __restrict__ sym,  float* __restrict__ out)
{
    const int b     = blockIdx.x;
    const int chunk = blockIdx.y;
    const int tid   = threadIdx.x;

    // Packed target-rotated points:
    //   s_xy[i] = { (-2x_{2i}, -2x_{2i+1}), (-2y_{2i}, -2y_{2i+1}) }
    //   s_zw[i] = { (-2z_{2i}, -2z_{2i+1}), ( n_{2i},   n_{2i+1}) }   n = |pt|^2
    __shared__ ulonglong2 s_xy[NPAIR];
    __shared__ ulonglong2 s_zw[NPAIR];
    __shared__ float  s_R[18];           // Rp[0..8], Rt[9..17]
    __shared__ int    s_cls;
    __shared__ float  s_issym;
    __shared__ float  s_warp[NTHREADS / 32];

    if (tid == 0) {
        // argmax over weight[b, c, 0] (first-max, matching jnp.argmax)
        const float* w = wgt + b * 4 * NC;
        int cls = 0; float best = w[0];
        #pragma unroll
        for (int c = 1; c < NC; c++) {
            float v = w[4 * c];
            if (v > best) { best = v; cls = c; }
        }
        s_cls   = cls;
        s_issym = sym[cls];

        // predicted quaternion (normalized) -> Rp
        const float* qp = pred + b * 4 * NC + 4 * cls;
        float qw = qp[0], qx = qp[1], qy = qp[2], qz = qp[3];
        float inv = rsqrtf(qw*qw + qx*qx + qy*qy + qz*qz);
        qw *= inv; qx *= inv; qy *= inv; qz *= inv;
        s_R[0] = 1.f - 2.f*(qy*qy + qz*qz); s_R[1] = 2.f*(qx*qy - qw*qz); s_R[2] = 2.f*(qx*qz + qw*qy);
        s_R[3] = 2.f*(qx*qy + qw*qz); s_R[4] = 1.f - 2.f*(qx*qx + qz*qz); s_R[5] = 2.f*(qy*qz - qw*qx);
        s_R[6] = 2.f*(qx*qz - qw*qy); s_R[7] = 2.f*(qy*qz + qw*qx); s_R[8] = 1.f - 2.f*(qx*qx + qy*qy);

        // target quaternion (already unit-norm) -> Rt
        const float* qt = tgt + b * 4 * NC + 4 * cls;
        qw = qt[0]; qx = qt[1]; qy = qt[2]; qz = qt[3];
        s_R[ 9] = 1.f - 2.f*(qy*qy + qz*qz); s_R[10] = 2.f*(qx*qy - qw*qz); s_R[11] = 2.f*(qx*qz + qw*qy);
        s_R[12] = 2.f*(qx*qy + qw*qz); s_R[13] = 1.f - 2.f*(qx*qx + qz*qz); s_R[14] = 2.f*(qy*qz - qw*qx);
        s_R[15] = 2.f*(qx*qz - qw*qy); s_R[16] = 2.f*(qy*qz + qw*qx); s_R[17] = 1.f - 2.f*(qx*qx + qy*qy);
    }
    __syncthreads();

    const int cls = s_cls;
    const float* pts = points + (size_t)cls * NP * 3;

    // Rotate all P points by Rt, pack pairs into smem
    {
        const float r0 = s_R[ 9], r1 = s_R[10], r2 = s_R[11];
        const float r3 = s_R[12], r4 = s_R[13], r5 = s_R[14];
        const float r6 = s_R[15], r7 = s_R[16], r8 = s_R[17];
        for (int i = tid; i < NPAIR; i += NTHREADS) {
            int q0 = 2 * i;
            float x0 = pts[3*q0+0], y0 = pts[3*q0+1], z0 = pts[3*q0+2];
            float x1 = pts[3*q0+3], y1 = pts[3*q0+4], z1 = pts[3*q0+5];
            float tx0 = r0*x0 + r1*y0 + r2*z0, tx1 = r0*x1 + r1*y1 + r2*z1;
            float ty0 = r3*x0 + r4*y0 + r5*z0, ty1 = r3*x1 + r4*y1 + r5*z1;
            float tz0 = r6*x0 + r7*y0 + r8*z0, tz1 = r6*x1 + r7*y1 + r8*z1;
            float n0 = tx0*tx0 + ty0*ty0 + tz0*tz0;
            float n1 = tx1*tx1 + ty1*ty1 + tz1*tz1;
            ulonglong2 xy, zw;
            xy.x = pack2(-2.f*tx0, -2.f*tx1);
            xy.y = pack2(-2.f*ty0, -2.f*ty1);
            zw.x = pack2(-2.f*tz0, -2.f*tz1);
            zw.y = pack2(n0, n1);
            s_xy[i] = xy;
            s_zw[i] = zw;
        }
    }
    __syncthreads();

    // This thread's predicted-rotated point
    const int p = chunk * NTHREADS + tid;
    float ppx, ppy, ppz;
    {
        const float r0 = s_R[0], r1 = s_R[1], r2 = s_R[2];
        const float r3 = s_R[3], r4 = s_R[4], r5 = s_R[5];
        const float r6 = s_R[6], r7 = s_R[7], r8 = s_R[8];
        float x = pts[3*p], y = pts[3*p + 1], z = pts[3*p + 2];
        ppx = r0*x + r1*y + r2*z;
        ppy = r3*x + r4*y + r5*z;
        ppz = r6*x + r7*y + r8*z;
    }
    const float cp = ppx*ppx + ppy*ppy + ppz*ppz;

    float acc;
    if (s_issym > 0.f) {
        // |pp - pt_q|^2 = cp + (n_q - 2 pp.pt_q); min over q.
        const unsigned long long px2 = pack2(ppx, ppx);
        const unsigned long long py2 = pack2(ppy, ppy);
        const unsigned long long pz2 = pack2(ppz, ppz);
        const float BIG = 3.402823e38f;
        float m0 = BIG, m1 = BIG, m2 = BIG, m3 = BIG;
        #pragma unroll 8
        for (int i = 0; i < NPAIR; i += 2) {
            ulonglong2 xyA = s_xy[i],   zwA = s_zw[i];
            ulonglong2 xyB = s_xy[i+1], zwB = s_zw[i+1];
            unsigned long long vA = fma2(pz2, zwA.x, fma2(py2, xyA.y, fma2(px2, xyA.x, zwA.y)));
            unsigned long long vB = fma2(pz2, zwB.x, fma2(py2, xyB.y, fma2(px2, xyB.x, zwB.y)));
            float a0, a1, b0, b1;
            unpack2(vA, a0, a1);
            unpack2(vB, b0, b1);
            m0 = fminf(m0, a0);
            m1 = fminf(m1, a1);
            m2 = fminf(m2, b0);
            m3 = fminf(m3, b1);
        }
        acc = cp + fminf(fminf(m0, m1), fminf(m2, m3));
    } else {
        // pointwise |pp_p - pt_p|^2 = cp + (n_p - 2 pp.pt_p) : same expansion at q=p
        int i = p >> 1, lane = p & 1;
        ulonglong2 xy = s_xy[i], zw = s_zw[i];
        float x0, x1, y0, y1, z0, z1, n0, n1;
        unpack2(xy.x, x0, x1);
        unpack2(xy.y, y0, y1);
        unpack2(zw.x, z0, z1);
        unpack2(zw.y, n0, n1);
        float xm = lane ? x1 : x0, ym = lane ? y1 : y0;
        float zm = lane ? z1 : z0, nn = lane ? n1 : n0;
        acc = cp + fmaf(ppx, xm, fmaf(ppy, ym, fmaf(ppz, zm, nn)));
    }

    // Block reduction
    float s = warp_reduce_sum(acc);
    if ((tid & 31) == 0) s_warp[tid >> 5] = s;
    __syncthreads();
    if (tid == 0) {
        float v = s_warp[0];
        #pragma unroll
        for (int wdx = 1; wdx < NTHREADS / 32; wdx++) v += s_warp[wdx];

        // Deterministic fixed-point accumulation (integer adds are associative)
        long long fx = __double2ll_rn((double)v * FXSCALE);
        atomicAdd(&g_acc, (unsigned long long)fx);
        __threadfence();
        unsigned int ticket = atomicAdd(&g_count, 1u);
        if (ticket == NBLOCKS - 1) {
            long long total = (long long)atomicAdd(&g_acc, 0ULL);
            out[0] = (float)((double)total / FXSCALE
                             * (1.0 / (2.0 * (double)NB * (double)NP)));
            // reset for next graph replay (deterministic re-entry)
            g_acc   = 0ULL;
            __threadfence();
            g_count = 0u;
        }
    }
}

extern "C" void kernel_launch(void* const* d_in, const int* in_sizes, int n_in,
                              void* d_out, int out_size) {
    const float* pred = (const float*)d_in[0];
    const float* tgt  = (const float*)d_in[1];
    const float* wgt  = (const float*)d_in[2];
    const float* pts  = (const float*)d_in[3];
    const float* sym  = (const float*)d_in[4];

    dim3 grid(NB, NCHUNK);
    pm_loss_main<<<grid, NTHREADS>>>(pred, tgt, wgt, pts, sym, (float*)d_out);
}